// round 16
// baseline (speedup 1.0000x reference)
#include <cuda_runtime.h>
#include <cuda_fp16.h>
#include <cstdint>

#define D 128
#define MAX_NODES 50048
#define MAX_E     1048576
#define SCAN_B 256
#define NBMAX 256
#define GP 20              // uint32 (half2) row stride in GEMM smem (conflict-free)

// Scratch (allocation-free rule: __device__ globals)
__device__ __half g_fph[MAX_NODES * D];    // F' = feature @ W^T, fp16
__device__ int   g_count[MAX_NODES];       // zero at load; re-zeroed in phase 3
__device__ int   g_rank[MAX_E];            // per-edge within-bin rank
__device__ int   g_excl[MAX_NODES];
__device__ int   g_bsum[NBMAX];
__device__ int   g_start[MAX_NODES + 1];
__device__ int2  g_edges[MAX_E];           // packed {src, w_bits} binned by dst
__device__ int   g_bar[4];                 // spin-barrier counters (self-resetting)

// ---------------------------------------------------------------------------
// Fused binning kernel: hist -> scan -> finalize -> permute, one launch.
// grid = NB (<=196) blocks of 256 threads; all CTAs co-resident (regs ~24),
// so global spin barriers are safe.  Counters reset with staggered scheme:
// counter k is reset only after barrier k+1 has completed (no spinner left).
// ---------------------------------------------------------------------------
__device__ __forceinline__ void grid_barrier(int idx, int nb) {
    __syncthreads();
    if (threadIdx.x == 0) {
        __threadfence();
        atomicAdd(&g_bar[idx], 1);
        while (*(volatile int*)&g_bar[idx] < nb) __nanosleep(64);
        __threadfence();
    }
    __syncthreads();
}

__global__ void __launch_bounds__(SCAN_B)
binning_fused_kernel(const int* __restrict__ src,
                     const int* __restrict__ dst,
                     const float* __restrict__ w,
                     int E, int N, int NB) {
    int t   = threadIdx.x;
    int bid = blockIdx.x;
    int gt  = bid * SCAN_B + t;
    int gs  = NB * SCAN_B;

    // ---- Phase 1: histogram + rank (grid-stride over edges) ----
    for (int e = gt; e < E; e += gs)
        g_rank[e] = atomicAdd(&g_count[dst[e]], 1);

    grid_barrier(0, NB);

    // ---- Phase 2: per-block 256-wide exclusive scan of counts ----
    {
        __shared__ int sh[SCAN_B];
        int i = bid * SCAN_B + t;
        int v = (i < N) ? g_count[i] : 0;
        sh[t] = v;
        __syncthreads();
#pragma unroll
        for (int off = 1; off < SCAN_B; off <<= 1) {
            int u = (t >= off) ? sh[t - off] : 0;
            __syncthreads();
            sh[t] += u;
            __syncthreads();
        }
        if (i < N) g_excl[i] = sh[t] - v;
        if (t == SCAN_B - 1) g_bsum[bid] = sh[SCAN_B - 1];
    }

    grid_barrier(1, NB);
    if (bid == 0 && t == 0) g_bar[0] = 0;    // safe: all passed barrier 0

    // ---- Phase 3: every block scans the <=256 block sums, finalizes ----
    {
        __shared__ int sh[NBMAX];
        __shared__ int orig[NBMAX];
        int v = (t < NB) ? g_bsum[t] : 0;
        sh[t] = v;
        orig[t] = v;
        __syncthreads();
#pragma unroll
        for (int off = 1; off < NBMAX; off <<= 1) {
            int u = (t >= off) ? sh[t - off] : 0;
            __syncthreads();
            sh[t] += u;
            __syncthreads();
        }
        int boff = sh[bid] - orig[bid];
        if (bid == 0 && t == 0) g_start[N] = sh[NBMAX - 1];

        int i = bid * SCAN_B + t;
        if (i < N) {
            g_start[i] = g_excl[i] + boff;
            g_count[i] = 0;    // reset for next graph replay
        }
    }

    grid_barrier(2, NB);
    if (bid == 0 && t == 0) g_bar[1] = 0;    // safe: all passed barrier 1

    // ---- Phase 4: atomic-free permute (grid-stride over edges) ----
    for (int e = gt; e < E; e += gs) {
        int pos = g_start[dst[e]] + g_rank[e];
        g_edges[pos] = make_int2(src[e], __float_as_int(w[e]));
    }

    // final arrival; block 0 resets remaining counters after everyone is done
    __syncthreads();
    if (t == 0) {
        __threadfence();
        atomicAdd(&g_bar[3], 1);
        if (bid == 0) {
            while (*(volatile int*)&g_bar[3] < NB) __nanosleep(64);
            g_bar[2] = 0;
            g_bar[3] = 0;
            __threadfence();
        }
    }
}

// ---------------------------------------------------------------------------
// Tensor-core GEMM: F' = feature @ W^T, fp16 hi/lo split, fp32 accumulate.
// 512 threads / 16 warps, warp tile 32x32 (R15 config).
// ---------------------------------------------------------------------------
__device__ __forceinline__ uint32_t pack2(__half a, __half b) {
    __half2 h = __halves2half2(a, b);
    return *(uint32_t*)&h;
}

__device__ __forceinline__ void mma16816(float* c, const uint32_t* a,
                                         uint32_t b0, uint32_t b1) {
    asm volatile(
        "mma.sync.aligned.m16n8k16.row.col.f32.f16.f16.f32 "
        "{%0,%1,%2,%3}, {%4,%5,%6,%7}, {%8,%9}, {%0,%1,%2,%3};"
        : "+f"(c[0]), "+f"(c[1]), "+f"(c[2]), "+f"(c[3])
        : "r"(a[0]), "r"(a[1]), "r"(a[2]), "r"(a[3]), "r"(b0), "r"(b1));
}

__global__ void __launch_bounds__(512)
gemm_tc_kernel(const float* __restrict__ A,
               const float* __restrict__ Wm,
               int M) {
    __shared__ uint32_t sAhi[128 * GP];
    __shared__ uint32_t sAlo[128 * GP];
    __shared__ uint32_t sWhi[128 * GP];
    __shared__ uint32_t sWlo[128 * GP];

    int tid  = threadIdx.x;
    int wid  = tid >> 5;
    int lane = tid & 31;
    int wr = (wid & 3) * 32;
    int wc = (wid >> 2) * 32;
    int lr = lane >> 2;
    int lc = lane & 3;
    int br = blockIdx.x * 128;

    float c[2][4][4];
#pragma unroll
    for (int mt = 0; mt < 2; mt++)
#pragma unroll
        for (int nt = 0; nt < 4; nt++)
#pragma unroll
            for (int q = 0; q < 4; q++) c[mt][nt][q] = 0.f;

    for (int kt = 0; kt < D; kt += 32) {
        __syncthreads();
#pragma unroll
        for (int it = 0; it < 4; it++) {
            int idx = tid + it * 512;
            int m = idx >> 4;
            int p = idx & 15;

            float2 fa = make_float2(0.f, 0.f);
            if (br + m < M)
                fa = *(const float2*)(A + (size_t)(br + m) * D + kt + p * 2);
            __half hx = __float2half_rn(fa.x);
            __half hy = __float2half_rn(fa.y);
            __half ox = __float2half_rn(fa.x - __half2float(hx));
            __half oy = __float2half_rn(fa.y - __half2float(hy));
            sAhi[m * GP + p] = pack2(hx, hy);
            sAlo[m * GP + p] = pack2(ox, oy);

            float2 fw = *(const float2*)(Wm + (size_t)m * D + kt + p * 2);
            __half wx = __float2half_rn(fw.x);
            __half wy = __float2half_rn(fw.y);
            __half vx = __float2half_rn(fw.x - __half2float(wx));
            __half vy = __float2half_rn(fw.y - __half2float(wy));
            sWhi[m * GP + p] = pack2(wx, wy);
            sWlo[m * GP + p] = pack2(vx, vy);
        }
        __syncthreads();

#pragma unroll
        for (int k2 = 0; k2 < 16; k2 += 8) {
            uint32_t ahi[2][4], alo[2][4];
#pragma unroll
            for (int mt = 0; mt < 2; mt++) {
                int r0 = wr + mt * 16 + lr;
                ahi[mt][0] = sAhi[r0 * GP + k2 + lc];
                ahi[mt][1] = sAhi[(r0 + 8) * GP + k2 + lc];
                ahi[mt][2] = sAhi[r0 * GP + k2 + 4 + lc];
                ahi[mt][3] = sAhi[(r0 + 8) * GP + k2 + 4 + lc];
                alo[mt][0] = sAlo[r0 * GP + k2 + lc];
                alo[mt][1] = sAlo[(r0 + 8) * GP + k2 + lc];
                alo[mt][2] = sAlo[r0 * GP + k2 + 4 + lc];
                alo[mt][3] = sAlo[(r0 + 8) * GP + k2 + 4 + lc];
            }
#pragma unroll
            for (int nt = 0; nt < 4; nt++) {
                int nr = wc + nt * 8 + lr;
                uint32_t bh0 = sWhi[nr * GP + k2 + lc];
                uint32_t bh1 = sWhi[nr * GP + k2 + 4 + lc];
                uint32_t bl0 = sWlo[nr * GP + k2 + lc];
                uint32_t bl1 = sWlo[nr * GP + k2 + 4 + lc];
#pragma unroll
                for (int mt = 0; mt < 2; mt++) {
                    mma16816(c[mt][nt], ahi[mt], bh0, bh1);
                    mma16816(c[mt][nt], ahi[mt], bl0, bl1);
                    mma16816(c[mt][nt], alo[mt], bh0, bh1);
                }
            }
        }
    }

#pragma unroll
    for (int mt = 0; mt < 2; mt++) {
#pragma unroll
        for (int nt = 0; nt < 4; nt++) {
            int m0  = br + wr + mt * 16 + lr;
            int col = wc + nt * 8 + lc * 2;
            if (m0 < M) {
                __half2 h = __floats2half2_rn(c[mt][nt][0], c[mt][nt][1]);
                *(uint32_t*)(g_fph + (size_t)m0 * D + col) = *(uint32_t*)&h;
            }
            if (m0 + 8 < M) {
                __half2 h = __floats2half2_rn(c[mt][nt][2], c[mt][nt][3]);
                *(uint32_t*)(g_fph + (size_t)(m0 + 8) * D + col) = *(uint32_t*)&h;
            }
        }
    }
}

// ---------------------------------------------------------------------------
// Aggregate + epilogue: warp/node, fp16 rows, fp32 accumulation.
// ---------------------------------------------------------------------------
__global__ void aggregate_out_kernel(const float* __restrict__ bias,
                                     float* __restrict__ out,
                                     int N) {
    int t = blockIdx.x * blockDim.x + threadIdx.x;
    int n = t >> 5;
    if (n >= N) return;
    int lane = t & 31;
    int col = lane * 4;

    int beg = g_start[n];
    int end = g_start[n + 1];

    float4 acc = make_float4(0.f, 0.f, 0.f, 0.f);
    int i = beg;
    for (; i + 3 < end; i += 4) {
        int2 p0 = __ldg(&g_edges[i]);
        int2 p1 = __ldg(&g_edges[i + 1]);
        int2 p2 = __ldg(&g_edges[i + 2]);
        int2 p3 = __ldg(&g_edges[i + 3]);
        uint2 u0 = *(const uint2*)(g_fph + (size_t)p0.x * D + col);
        uint2 u1 = *(const uint2*)(g_fph + (size_t)p1.x * D + col);
        uint2 u2 = *(const uint2*)(g_fph + (size_t)p2.x * D + col);
        uint2 u3 = *(const uint2*)(g_fph + (size_t)p3.x * D + col);
        float w0 = __int_as_float(p0.y);
        float w1 = __int_as_float(p1.y);
        float w2 = __int_as_float(p2.y);
        float w3 = __int_as_float(p3.y);

        float2 a0 = __half22float2(*(__half2*)&u0.x), b0 = __half22float2(*(__half2*)&u0.y);
        float2 a1 = __half22float2(*(__half2*)&u1.x), b1 = __half22float2(*(__half2*)&u1.y);
        float2 a2 = __half22float2(*(__half2*)&u2.x), b2 = __half22float2(*(__half2*)&u2.y);
        float2 a3 = __half22float2(*(__half2*)&u3.x), b3 = __half22float2(*(__half2*)&u3.y);

        acc.x += a0.x * w0 + a1.x * w1 + a2.x * w2 + a3.x * w3;
        acc.y += a0.y * w0 + a1.y * w1 + a2.y * w2 + a3.y * w3;
        acc.z += b0.x * w0 + b1.x * w1 + b2.x * w2 + b3.x * w3;
        acc.w += b0.y * w0 + b1.y * w1 + b2.y * w2 + b3.y * w3;
    }
    for (; i < end; i++) {
        int2 p0 = __ldg(&g_edges[i]);
        uint2 u0 = *(const uint2*)(g_fph + (size_t)p0.x * D + col);
        float w0 = __int_as_float(p0.y);
        float2 a0 = __half22float2(*(__half2*)&u0.x), b0 = __half22float2(*(__half2*)&u0.y);
        acc.x += a0.x * w0;
        acc.y += a0.y * w0;
        acc.z += b0.x * w0;
        acc.w += b0.y * w0;
    }

    float4 b4 = __ldg((const float4*)(bias + col));
    acc.x = fmaxf(acc.x + b4.x, 0.f);
    acc.y = fmaxf(acc.y + b4.y, 0.f);
    acc.z = fmaxf(acc.z + b4.z, 0.f);
    acc.w = fmaxf(acc.w + b4.w, 0.f);

    *(float4*)(out + (size_t)n * D + col) = acc;
}

// ---------------------------------------------------------------------------
// Launch: 3 kernels.  GEMM (side) ∥ binning_fused (main) → aggregate.
// ---------------------------------------------------------------------------
extern "C" void kernel_launch(void* const* d_in, const int* in_sizes, int n_in,
                              void* d_out, int out_size) {
    const float* feature = (const float*)d_in[0];
    const int*   src     = (const int*)d_in[1];
    const int*   dst     = (const int*)d_in[2];
    const float* w       = (const float*)d_in[3];
    const float* Wm      = (const float*)d_in[4];
    const float* bias    = (const float*)d_in[5];
    float*       out     = (float*)d_out;

    int M = in_sizes[0] / D;
    int E = in_sizes[1];
    if (E > MAX_E) E = MAX_E;

    static cudaStream_t s2 = nullptr;
    static cudaEvent_t evFork = nullptr, evGemm = nullptr;
    if (s2 == nullptr) {
        cudaStreamCreateWithFlags(&s2, cudaStreamNonBlocking);
        cudaEventCreateWithFlags(&evFork, cudaEventDisableTiming);
        cudaEventCreateWithFlags(&evGemm, cudaEventDisableTiming);
    }

    // Fork: tensor-core GEMM on side stream
    cudaEventRecord(evFork, 0);
    cudaStreamWaitEvent(s2, evFork, 0);
    gemm_tc_kernel<<<(M + 127) / 128, 512, 0, s2>>>(feature, Wm, M);
    cudaEventRecord(evGemm, s2);

    // Main stream: one fused binning kernel
    int NB = (M + SCAN_B - 1) / SCAN_B;    // 196 <= NBMAX
    binning_fused_kernel<<<NB, SCAN_B>>>(src, dst, w, E, M, NB);

    // Join, then aggregate + epilogue
    cudaStreamWaitEvent(0, evGemm, 0);
    long long agg_threads = (long long)M * 32;
    aggregate_out_kernel<<<(int)((agg_threads + 255) / 256), 256>>>(bias, out, M);
}

// round 17
// speedup vs baseline: 1.5036x; 1.5036x over previous
#include <cuda_runtime.h>
#include <cuda_fp16.h>
#include <cstdint>

#define D 128
#define MAX_NODES 50048
#define MAX_E     1048576
#define SCAN_B 256
#define MAX_SCAN_BLOCKS 256
#define GP 20              // uint32 (half2) row stride in GEMM smem (conflict-free)

// Scratch (allocation-free rule: __device__ globals)
__device__ __half g_fph[MAX_NODES * D];    // F' = feature @ W^T, fp16
__device__ int   g_count[MAX_NODES];       // zero at load; re-zeroed by scan23
__device__ int   g_rank[MAX_E];            // per-edge within-bin rank (from hist)
__device__ int   g_excl[MAX_NODES];
__device__ int   g_bsum[MAX_SCAN_BLOCKS];
__device__ int   g_start[MAX_NODES + 1];
__device__ int2  g_edges[MAX_E];           // packed {src, w_bits} binned by dst

// ---------------------------------------------------------------------------
// binning chain (R15, proven)
// ---------------------------------------------------------------------------
__global__ void hist_kernel(const int* __restrict__ dst, int E) {
    int e = blockIdx.x * blockDim.x + threadIdx.x;
    if (e < E) g_rank[e] = atomicAdd(&g_count[dst[e]], 1);
}

__global__ void scan1_kernel(int N) {
    __shared__ int sh[SCAN_B];
    int t = threadIdx.x;
    int i = blockIdx.x * SCAN_B + t;
    int v = (i < N) ? g_count[i] : 0;
    sh[t] = v;
    __syncthreads();
#pragma unroll
    for (int off = 1; off < SCAN_B; off <<= 1) {
        int u = (t >= off) ? sh[t - off] : 0;
        __syncthreads();
        sh[t] += u;
        __syncthreads();
    }
    if (i < N) g_excl[i] = sh[t] - v;
    if (t == SCAN_B - 1) g_bsum[blockIdx.x] = sh[SCAN_B - 1];
}

__global__ void scan23_kernel(int NB, int N) {
    __shared__ int sh[MAX_SCAN_BLOCKS];
    __shared__ int orig[MAX_SCAN_BLOCKS];
    int t = threadIdx.x;
    int v = (t < NB) ? g_bsum[t] : 0;
    sh[t] = v;
    orig[t] = v;
    __syncthreads();
#pragma unroll
    for (int off = 1; off < MAX_SCAN_BLOCKS; off <<= 1) {
        int u = (t >= off) ? sh[t - off] : 0;
        __syncthreads();
        sh[t] += u;
        __syncthreads();
    }
    int boff = sh[blockIdx.x] - orig[blockIdx.x];
    if (blockIdx.x == 0 && t == 0) g_start[N] = sh[MAX_SCAN_BLOCKS - 1];

    int i = blockIdx.x * SCAN_B + t;
    if (i < N) {
        g_start[i] = g_excl[i] + boff;
        g_count[i] = 0;    // reset for next graph replay
    }
}

__global__ void permute_kernel(const int* __restrict__ src,
                               const int* __restrict__ dst,
                               const float* __restrict__ w,
                               int E) {
    int e = blockIdx.x * blockDim.x + threadIdx.x;
    if (e < E) {
        int pos = g_start[dst[e]] + g_rank[e];
        g_edges[pos] = make_int2(src[e], __float_as_int(w[e]));
    }
}

// ---------------------------------------------------------------------------
// Tensor-core GEMM with software-pipelined K-loop.
// 512 threads / 16 warps, warp tile 32x32.  Register-prefetch of the next
// K-chunk's A/W float2s is issued before the current chunk's MMAs, hiding
// the DRAM latency under ~192 MMAs.
// ---------------------------------------------------------------------------
__device__ __forceinline__ uint32_t pack2(__half a, __half b) {
    __half2 h = __halves2half2(a, b);
    return *(uint32_t*)&h;
}

__device__ __forceinline__ void mma16816(float* c, const uint32_t* a,
                                         uint32_t b0, uint32_t b1) {
    asm volatile(
        "mma.sync.aligned.m16n8k16.row.col.f32.f16.f16.f32 "
        "{%0,%1,%2,%3}, {%4,%5,%6,%7}, {%8,%9}, {%0,%1,%2,%3};"
        : "+f"(c[0]), "+f"(c[1]), "+f"(c[2]), "+f"(c[3])
        : "r"(a[0]), "r"(a[1]), "r"(a[2]), "r"(a[3]), "r"(b0), "r"(b1));
}

__global__ void __launch_bounds__(512)
gemm_tc_kernel(const float* __restrict__ A,
               const float* __restrict__ Wm,
               int M) {
    __shared__ uint32_t sAhi[128 * GP];
    __shared__ uint32_t sAlo[128 * GP];
    __shared__ uint32_t sWhi[128 * GP];
    __shared__ uint32_t sWlo[128 * GP];

    int tid  = threadIdx.x;
    int wid  = tid >> 5;
    int lane = tid & 31;
    int wr = (wid & 3) * 32;
    int wc = (wid >> 2) * 32;
    int lr = lane >> 2;
    int lc = lane & 3;
    int br = blockIdx.x * 128;

    // per-thread fill coordinates (4 elements, fixed across chunks)
    int fm[4], fp[4];
    bool frow[4];
#pragma unroll
    for (int it = 0; it < 4; it++) {
        int idx = tid + it * 512;
        fm[it] = idx >> 4;
        fp[it] = idx & 15;
        frow[it] = (br + fm[it] < M);
    }

    float c[2][4][4];
#pragma unroll
    for (int mt = 0; mt < 2; mt++)
#pragma unroll
        for (int nt = 0; nt < 4; nt++)
#pragma unroll
            for (int q = 0; q < 4; q++) c[mt][nt][q] = 0.f;

    // prologue: load chunk 0 into registers
    float2 pa[4], pw[4];
#pragma unroll
    for (int it = 0; it < 4; it++) {
        pa[it] = frow[it] ? *(const float2*)(A + (size_t)(br + fm[it]) * D + fp[it] * 2)
                          : make_float2(0.f, 0.f);
        pw[it] = *(const float2*)(Wm + (size_t)fm[it] * D + fp[it] * 2);
    }

    for (int kt = 0; kt < D; kt += 32) {
        // convert prefetched regs -> smem
        __syncthreads();
#pragma unroll
        for (int it = 0; it < 4; it++) {
            float2 fa = pa[it];
            __half hx = __float2half_rn(fa.x);
            __half hy = __float2half_rn(fa.y);
            __half ox = __float2half_rn(fa.x - __half2float(hx));
            __half oy = __float2half_rn(fa.y - __half2float(hy));
            sAhi[fm[it] * GP + fp[it]] = pack2(hx, hy);
            sAlo[fm[it] * GP + fp[it]] = pack2(ox, oy);

            float2 fw = pw[it];
            __half wx = __float2half_rn(fw.x);
            __half wy = __float2half_rn(fw.y);
            __half vx = __float2half_rn(fw.x - __half2float(wx));
            __half vy = __float2half_rn(fw.y - __half2float(wy));
            sWhi[fm[it] * GP + fp[it]] = pack2(wx, wy);
            sWlo[fm[it] * GP + fp[it]] = pack2(vx, vy);
        }
        __syncthreads();

        // issue next chunk's loads EARLY (latency overlapped by MMAs below)
        int ktn = kt + 32;
        if (ktn < D) {
#pragma unroll
            for (int it = 0; it < 4; it++) {
                pa[it] = frow[it]
                    ? *(const float2*)(A + (size_t)(br + fm[it]) * D + ktn + fp[it] * 2)
                    : make_float2(0.f, 0.f);
                pw[it] = *(const float2*)(Wm + (size_t)fm[it] * D + ktn + fp[it] * 2);
            }
        }

#pragma unroll
        for (int k2 = 0; k2 < 16; k2 += 8) {
            uint32_t ahi[2][4], alo[2][4];
#pragma unroll
            for (int mt = 0; mt < 2; mt++) {
                int r0 = wr + mt * 16 + lr;
                ahi[mt][0] = sAhi[r0 * GP + k2 + lc];
                ahi[mt][1] = sAhi[(r0 + 8) * GP + k2 + lc];
                ahi[mt][2] = sAhi[r0 * GP + k2 + 4 + lc];
                ahi[mt][3] = sAhi[(r0 + 8) * GP + k2 + 4 + lc];
                alo[mt][0] = sAlo[r0 * GP + k2 + lc];
                alo[mt][1] = sAlo[(r0 + 8) * GP + k2 + lc];
                alo[mt][2] = sAlo[r0 * GP + k2 + 4 + lc];
                alo[mt][3] = sAlo[(r0 + 8) * GP + k2 + 4 + lc];
            }
#pragma unroll
            for (int nt = 0; nt < 4; nt++) {
                int nr = wc + nt * 8 + lr;
                uint32_t bh0 = sWhi[nr * GP + k2 + lc];
                uint32_t bh1 = sWhi[nr * GP + k2 + 4 + lc];
                uint32_t bl0 = sWlo[nr * GP + k2 + lc];
                uint32_t bl1 = sWlo[nr * GP + k2 + 4 + lc];
#pragma unroll
                for (int mt = 0; mt < 2; mt++) {
                    mma16816(c[mt][nt], ahi[mt], bh0, bh1);
                    mma16816(c[mt][nt], ahi[mt], bl0, bl1);
                    mma16816(c[mt][nt], alo[mt], bh0, bh1);
                }
            }
        }
    }

#pragma unroll
    for (int mt = 0; mt < 2; mt++) {
#pragma unroll
        for (int nt = 0; nt < 4; nt++) {
            int m0  = br + wr + mt * 16 + lr;
            int col = wc + nt * 8 + lc * 2;
            if (m0 < M) {
                __half2 h = __floats2half2_rn(c[mt][nt][0], c[mt][nt][1]);
                *(uint32_t*)(g_fph + (size_t)m0 * D + col) = *(uint32_t*)&h;
            }
            if (m0 + 8 < M) {
                __half2 h = __floats2half2_rn(c[mt][nt][2], c[mt][nt][3]);
                *(uint32_t*)(g_fph + (size_t)(m0 + 8) * D + col) = *(uint32_t*)&h;
            }
        }
    }
}

// ---------------------------------------------------------------------------
// Aggregate + epilogue: warp/node, fp16 rows, fp32 accumulation.
// ---------------------------------------------------------------------------
__global__ void aggregate_out_kernel(const float* __restrict__ bias,
                                     float* __restrict__ out,
                                     int N) {
    int t = blockIdx.x * blockDim.x + threadIdx.x;
    int n = t >> 5;
    if (n >= N) return;
    int lane = t & 31;
    int col = lane * 4;

    int beg = g_start[n];
    int end = g_start[n + 1];

    float4 acc = make_float4(0.f, 0.f, 0.f, 0.f);
    int i = beg;
    for (; i + 3 < end; i += 4) {
        int2 p0 = __ldg(&g_edges[i]);
        int2 p1 = __ldg(&g_edges[i + 1]);
        int2 p2 = __ldg(&g_edges[i + 2]);
        int2 p3 = __ldg(&g_edges[i + 3]);
        uint2 u0 = *(const uint2*)(g_fph + (size_t)p0.x * D + col);
        uint2 u1 = *(const uint2*)(g_fph + (size_t)p1.x * D + col);
        uint2 u2 = *(const uint2*)(g_fph + (size_t)p2.x * D + col);
        uint2 u3 = *(const uint2*)(g_fph + (size_t)p3.x * D + col);
        float w0 = __int_as_float(p0.y);
        float w1 = __int_as_float(p1.y);
        float w2 = __int_as_float(p2.y);
        float w3 = __int_as_float(p3.y);

        float2 a0 = __half22float2(*(__half2*)&u0.x), b0 = __half22float2(*(__half2*)&u0.y);
        float2 a1 = __half22float2(*(__half2*)&u1.x), b1 = __half22float2(*(__half2*)&u1.y);
        float2 a2 = __half22float2(*(__half2*)&u2.x), b2 = __half22float2(*(__half2*)&u2.y);
        float2 a3 = __half22float2(*(__half2*)&u3.x), b3 = __half22float2(*(__half2*)&u3.y);

        acc.x += a0.x * w0 + a1.x * w1 + a2.x * w2 + a3.x * w3;
        acc.y += a0.y * w0 + a1.y * w1 + a2.y * w2 + a3.y * w3;
        acc.z += b0.x * w0 + b1.x * w1 + b2.x * w2 + b3.x * w3;
        acc.w += b0.y * w0 + b1.y * w1 + b2.y * w2 + b3.y * w3;
    }
    for (; i < end; i++) {
        int2 p0 = __ldg(&g_edges[i]);
        uint2 u0 = *(const uint2*)(g_fph + (size_t)p0.x * D + col);
        float w0 = __int_as_float(p0.y);
        float2 a0 = __half22float2(*(__half2*)&u0.x), b0 = __half22float2(*(__half2*)&u0.y);
        acc.x += a0.x * w0;
        acc.y += a0.y * w0;
        acc.z += b0.x * w0;
        acc.w += b0.y * w0;
    }

    float4 b4 = __ldg((const float4*)(bias + col));
    acc.x = fmaxf(acc.x + b4.x, 0.f);
    acc.y = fmaxf(acc.y + b4.y, 0.f);
    acc.z = fmaxf(acc.z + b4.z, 0.f);
    acc.w = fmaxf(acc.w + b4.w, 0.f);

    *(float4*)(out + (size_t)n * D + col) = acc;
}

// ---------------------------------------------------------------------------
// Launch: fork-join (R15 structure).
// ---------------------------------------------------------------------------
extern "C" void kernel_launch(void* const* d_in, const int* in_sizes, int n_in,
                              void* d_out, int out_size) {
    const float* feature = (const float*)d_in[0];
    const int*   src     = (const int*)d_in[1];
    const int*   dst     = (const int*)d_in[2];
    const float* w       = (const float*)d_in[3];
    const float* Wm      = (const float*)d_in[4];
    const float* bias    = (const float*)d_in[5];
    float*       out     = (float*)d_out;

    int M = in_sizes[0] / D;
    int E = in_sizes[1];
    if (E > MAX_E) E = MAX_E;

    static cudaStream_t s2 = nullptr;
    static cudaEvent_t evFork = nullptr, evGemm = nullptr;
    if (s2 == nullptr) {
        cudaStreamCreateWithFlags(&s2, cudaStreamNonBlocking);
        cudaEventCreateWithFlags(&evFork, cudaEventDisableTiming);
        cudaEventCreateWithFlags(&evGemm, cudaEventDisableTiming);
    }

    // Fork: pipelined tensor-core GEMM on side stream
    cudaEventRecord(evFork, 0);
    cudaStreamWaitEvent(s2, evFork, 0);
    gemm_tc_kernel<<<(M + 127) / 128, 512, 0, s2>>>(feature, Wm, M);
    cudaEventRecord(evGemm, s2);

    // Main stream: binning chain
    int NB = (M + SCAN_B - 1) / SCAN_B;
    hist_kernel<<<(E + 255) / 256, 256>>>(dst, E);
    scan1_kernel<<<NB, SCAN_B>>>(M);
    scan23_kernel<<<NB, SCAN_B>>>(NB, M);
    permute_kernel<<<(E + 255) / 256, 256>>>(src, dst, w, E);

    // Join, then aggregate + epilogue
    cudaStreamWaitEvent(0, evGemm, 0);
    long long agg_threads = (long long)M * 32;
    aggregate_out_kernel<<<(int)((agg_threads + 255) / 256), 256>>>(bias, out, M);
}